// round 10
// baseline (speedup 1.0000x reference)
#include <cuda_runtime.h>
#include <cuda_bf16.h>
#include <cstdint>

// LeftPool: out[b,c,h,w] = max(x[b,c,h,w:]) — reverse cummax along width (=128, contiguous).
//
// One warp per FOUR CONSECUTIVE rows (4g..4g+3): the warp's entire footprint is
// one contiguous 2KB chunk (block: 16KB contiguous) for both the read and write
// streams — minimal concurrent-stream count, maximal DRAM row-buffer locality.
// Front-batched loads (MLP=4/thread), 4 independent suffix-scan chains hide
// SHFL latency. Streaming (evict-first) hints: zero reuse.

__global__ void __launch_bounds__(256) leftpool_kernel(
    const float4* __restrict__ x, float4* __restrict__ out, int q)
{
    const int gwarp = (int)((blockIdx.x * blockDim.x + threadIdx.x) >> 5);
    const int lane  = threadIdx.x & 31;
    if (gwarp >= q) return;

    // 4 consecutive rows: float4 indices gwarp*128 + {0,32,64,96} + lane
    const size_t b0 = (size_t)gwarp * 128 + lane;
    const size_t b1 = b0 + 32;
    const size_t b2 = b0 + 64;
    const size_t b3 = b0 + 96;

    // Front-batch all loads, streaming (evict-first) policy.
    float4 v0 = __ldcs(&x[b0]);
    float4 v1 = __ldcs(&x[b1]);
    float4 v2 = __ldcs(&x[b2]);
    float4 v3 = __ldcs(&x[b3]);

    // In-lane suffix max (4 independent chains).
    v0.z = fmaxf(v0.z, v0.w);  v1.z = fmaxf(v1.z, v1.w);
    v2.z = fmaxf(v2.z, v2.w);  v3.z = fmaxf(v3.z, v3.w);
    v0.y = fmaxf(v0.y, v0.z);  v1.y = fmaxf(v1.y, v1.z);
    v2.y = fmaxf(v2.y, v2.z);  v3.y = fmaxf(v3.y, v3.z);
    v0.x = fmaxf(v0.x, v0.y);  v1.x = fmaxf(v1.x, v1.y);
    v2.x = fmaxf(v2.x, v2.y);  v3.x = fmaxf(v3.x, v3.y);

    // Inclusive suffix max across lanes; 4 chains in parallel.
    float m0 = v0.x, m1 = v1.x, m2 = v2.x, m3 = v3.x;
    #pragma unroll
    for (int d = 1; d < 32; d <<= 1) {
        float t0 = __shfl_down_sync(0xffffffffu, m0, d);
        float t1 = __shfl_down_sync(0xffffffffu, m1, d);
        float t2 = __shfl_down_sync(0xffffffffu, m2, d);
        float t3 = __shfl_down_sync(0xffffffffu, m3, d);
        m0 = fmaxf(m0, t0);   // out-of-range shfl returns own value -> harmless
        m1 = fmaxf(m1, t1);
        m2 = fmaxf(m2, t2);
        m3 = fmaxf(m3, t3);
    }
    // Exclusive suffix: shift down by one; lane 31 sees -inf.
    float s0 = __shfl_down_sync(0xffffffffu, m0, 1);
    float s1 = __shfl_down_sync(0xffffffffu, m1, 1);
    float s2 = __shfl_down_sync(0xffffffffu, m2, 1);
    float s3 = __shfl_down_sync(0xffffffffu, m3, 1);
    if (lane == 31) {
        const float ninf = __int_as_float(0xff800000u);
        s0 = ninf; s1 = ninf; s2 = ninf; s3 = ninf;
    }

    v0.x = fmaxf(v0.x, s0);  v1.x = fmaxf(v1.x, s1);
    v2.x = fmaxf(v2.x, s2);  v3.x = fmaxf(v3.x, s3);
    v0.y = fmaxf(v0.y, s0);  v1.y = fmaxf(v1.y, s1);
    v2.y = fmaxf(v2.y, s2);  v3.y = fmaxf(v3.y, s3);
    v0.z = fmaxf(v0.z, s0);  v1.z = fmaxf(v1.z, s1);
    v2.z = fmaxf(v2.z, s2);  v3.z = fmaxf(v3.z, s3);
    v0.w = fmaxf(v0.w, s0);  v1.w = fmaxf(v1.w, s1);
    v2.w = fmaxf(v2.w, s2);  v3.w = fmaxf(v3.w, s3);

    // Streaming stores (evict-first), same contiguous 2KB chunk.
    __stcs(&out[b0], v0);
    __stcs(&out[b1], v1);
    __stcs(&out[b2], v2);
    __stcs(&out[b3], v3);
}

extern "C" void kernel_launch(void* const* d_in, const int* in_sizes, int n_in,
                              void* d_out, int out_size)
{
    const float* x = (const float*)d_in[0];
    float* out = (float*)d_out;

    const int W = 128;                          // contiguous width axis
    const int nrows = in_sizes[0] / W;          // 524288
    const int q = nrows / 4;                    // 131072 warps, 4 consecutive rows each

    const int threads = 256;                    // 8 warps/block -> 16KB contiguous per block
    const int warps_per_block = threads / 32;
    const int blocks = (q + warps_per_block - 1) / warps_per_block;  // 16384

    leftpool_kernel<<<blocks, threads>>>(
        (const float4*)x, (float4*)out, q);
}

// round 11
// speedup vs baseline: 1.0086x; 1.0086x over previous
#include <cuda_runtime.h>
#include <cuda_bf16.h>
#include <cstdint>

// LeftPool: out[b,c,h,w] = max(x[b,c,h,w:]) — reverse cummax along width (=128, contiguous).
//
// Best-known config (R6 revert + polish): one warp per FOUR rows strided by
// q = nrows/4 (4 independent 64MB-apart streams per warp -> spreads requests
// across all LTS slices / HBM channels; verified better than consecutive rows
// in R10). Front-batched loads (MLP=4/thread); 4 independent suffix-scan
// chains hide SHFL latency. 512-thread blocks, exact grid (no guard).

__global__ void __launch_bounds__(512) leftpool_kernel(
    const float4* __restrict__ x, float4* __restrict__ out, int q)
{
    const int gwarp = (int)((blockIdx.x * blockDim.x + threadIdx.x) >> 5);
    const int lane  = threadIdx.x & 31;

    const size_t stride = (size_t)q * 32;
    const size_t b0 = (size_t)gwarp * 32 + lane;     // float4 index, row g
    const size_t b1 = b0 + stride;
    const size_t b2 = b1 + stride;
    const size_t b3 = b2 + stride;

    // Front-batch all loads before any dependent work.
    float4 v0 = x[b0];
    float4 v1 = x[b1];
    float4 v2 = x[b2];
    float4 v3 = x[b3];

    // In-lane suffix max (4 independent chains).
    v0.z = fmaxf(v0.z, v0.w);  v1.z = fmaxf(v1.z, v1.w);
    v2.z = fmaxf(v2.z, v2.w);  v3.z = fmaxf(v3.z, v3.w);
    v0.y = fmaxf(v0.y, v0.z);  v1.y = fmaxf(v1.y, v1.z);
    v2.y = fmaxf(v2.y, v2.z);  v3.y = fmaxf(v3.y, v3.z);
    v0.x = fmaxf(v0.x, v0.y);  v1.x = fmaxf(v1.x, v1.y);
    v2.x = fmaxf(v2.x, v2.y);  v3.x = fmaxf(v3.x, v3.y);

    // Inclusive suffix max across lanes; 4 chains in parallel.
    float m0 = v0.x, m1 = v1.x, m2 = v2.x, m3 = v3.x;
    #pragma unroll
    for (int d = 1; d < 32; d <<= 1) {
        float t0 = __shfl_down_sync(0xffffffffu, m0, d);
        float t1 = __shfl_down_sync(0xffffffffu, m1, d);
        float t2 = __shfl_down_sync(0xffffffffu, m2, d);
        float t3 = __shfl_down_sync(0xffffffffu, m3, d);
        m0 = fmaxf(m0, t0);   // out-of-range shfl returns own value -> harmless
        m1 = fmaxf(m1, t1);
        m2 = fmaxf(m2, t2);
        m3 = fmaxf(m3, t3);
    }
    // Exclusive suffix: shift down by one; lane 31 sees -inf.
    float s0 = __shfl_down_sync(0xffffffffu, m0, 1);
    float s1 = __shfl_down_sync(0xffffffffu, m1, 1);
    float s2 = __shfl_down_sync(0xffffffffu, m2, 1);
    float s3 = __shfl_down_sync(0xffffffffu, m3, 1);
    if (lane == 31) {
        const float ninf = __int_as_float(0xff800000u);
        s0 = ninf; s1 = ninf; s2 = ninf; s3 = ninf;
    }

    v0.x = fmaxf(v0.x, s0);  v1.x = fmaxf(v1.x, s1);
    v2.x = fmaxf(v2.x, s2);  v3.x = fmaxf(v3.x, s3);
    v0.y = fmaxf(v0.y, s0);  v1.y = fmaxf(v1.y, s1);
    v2.y = fmaxf(v2.y, s2);  v3.y = fmaxf(v3.y, s3);
    v0.z = fmaxf(v0.z, s0);  v1.z = fmaxf(v1.z, s1);
    v2.z = fmaxf(v2.z, s2);  v3.z = fmaxf(v3.z, s3);
    v0.w = fmaxf(v0.w, s0);  v1.w = fmaxf(v1.w, s1);
    v2.w = fmaxf(v2.w, s2);  v3.w = fmaxf(v3.w, s3);

    out[b0] = v0;
    out[b1] = v1;
    out[b2] = v2;
    out[b3] = v3;
}

extern "C" void kernel_launch(void* const* d_in, const int* in_sizes, int n_in,
                              void* d_out, int out_size)
{
    const float* x = (const float*)d_in[0];
    float* out = (float*)d_out;

    const int W = 128;                          // contiguous width axis
    const int nrows = in_sizes[0] / W;          // 524288
    const int q = nrows / 4;                    // 131072 warps, 4 rows each

    const int threads = 512;                    // 16 warps/block
    const int blocks = q / (threads / 32);      // 8192, divides exactly

    leftpool_kernel<<<blocks, threads>>>(
        (const float4*)x, (float4*)out, q);
}